// round 15
// baseline (speedup 1.0000x reference)
#include <cuda_runtime.h>
#include <cuda_bf16.h>
#include <cstddef>

#define BB 2048
#define NN 512
#define XX 32
#define HH 64
#define TILE_B 16
#define THREADS 256
#define NBLK (BB / TILE_B)   /* 128 */
#define AXP 40               /* x operand pitch (bf16) */
#define AHP 72               /* h operand pitch (bf16) */

__device__ __forceinline__ float sigmoidf_fast(float x) {
    return __fdividef(1.0f, 1.0f + __expf(-x));
}
__device__ __forceinline__ float tanhf_fast(float x) {
    return __fdividef(2.0f, 1.0f + __expf(-2.0f * x)) - 1.0f;
}
__device__ __forceinline__ unsigned bfpack(__nv_bfloat16 a, __nv_bfloat16 b) {
    __nv_bfloat162 t;
    t.x = a; t.y = b;
    return *reinterpret_cast<unsigned*>(&t);
}
__device__ __forceinline__ void bsplit(float v, __nv_bfloat16& bh, __nv_bfloat16& bl) {
    bh = __float2bfloat16_rn(v);
    bl = __float2bfloat16_rn(v - __bfloat162float(bh));
}
__device__ __forceinline__ void mma16816(float* c, const unsigned* a, const unsigned* b) {
    asm volatile(
        "mma.sync.aligned.m16n8k16.row.col.f32.bf16.bf16.f32 "
        "{%0,%1,%2,%3}, {%4,%5,%6,%7}, {%8,%9}, {%0,%1,%2,%3};"
        : "+f"(c[0]), "+f"(c[1]), "+f"(c[2]), "+f"(c[3])
        : "r"(a[0]), "r"(a[1]), "r"(a[2]), "r"(a[3]), "r"(b[0]), "r"(b[1]));
}
__device__ __forceinline__ unsigned long long packf2(float x, float y) {
    unsigned long long r;
    asm("mov.b64 %0, {%1, %2};" : "=l"(r) : "f"(x), "f"(y));
    return r;
}
__device__ __forceinline__ void unpackf2(unsigned long long v, float& x, float& y) {
    asm("mov.b64 {%0, %1}, %2;" : "=f"(x), "=f"(y) : "l"(v));
}

__global__ void __launch_bounds__(THREADS, 1)
timelstm_tc_kernel(const float* __restrict__ x,
                   const float* __restrict__ ig_w_c, const float* __restrict__ ig_w_h,
                   const float* __restrict__ ig_w_x, const float* __restrict__ ig_b,
                   const float* __restrict__ fg_w_c, const float* __restrict__ fg_w_h,
                   const float* __restrict__ fg_w_x, const float* __restrict__ fg_b,
                   const float* __restrict__ in_w_h, const float* __restrict__ in_w_x,
                   const float* __restrict__ in_b,
                   const float* __restrict__ og_w_cn, const float* __restrict__ og_w_h,
                   const float* __restrict__ og_w_x, const float* __restrict__ og_b,
                   float* __restrict__ out)
{
    // x: triple-buffered; h: ping-pong
    __shared__ __align__(16) __nv_bfloat16 Axhi[3][TILE_B][AXP];
    __shared__ __align__(16) __nv_bfloat16 Axlo[3][TILE_B][AXP];
    __shared__ __align__(16) __nv_bfloat16 Ahhi[2][TILE_B][AHP];
    __shared__ __align__(16) __nv_bfloat16 Ahlo[2][TILE_B][AHP];

    const int tid  = threadIdx.x;
    const int b0   = blockIdx.x * TILE_B;
    const int w    = tid >> 5;           // warp 0..7: n-range [32w, 32w+32)
    const int lane = tid & 31;
    const int jn = lane >> 2;            // 0..7
    const int jk = (lane & 3) * 2;       // 0,2,4,6
    const int pr = lane & 1;             // phase-B row select: jn + 8*pr
    const bool sel01 = ((jk & 3) == 0);  // own gates {0,1} vs {2,3}

    // ---- B fragments: n = 4*ch + gate ordering ----
    // B frag thread mapping: n_local = jn, k = kt*16 + jk (+8 per reg).
    // gate = jn&3, ch = 8w + 2nt + (jn>>2).
    const float* Wxs[4] = {ig_w_x, fg_w_x, in_w_x, og_w_x};
    const float* Whs[4] = {ig_w_h, fg_w_h, in_w_h, og_w_h};
    const float* WxG = Wxs[jn & 3];
    const float* WhG = Whs[jn & 3];

    unsigned Bh[6][4][2], Bl[6][4][2];
    #pragma unroll
    for (int kt = 0; kt < 6; kt++) {
        #pragma unroll
        for (int nt = 0; nt < 4; nt++) {
            const int ch = 8 * w + 2 * nt + (jn >> 2);
            #pragma unroll
            for (int r = 0; r < 2; r++) {
                const int k0 = kt * 16 + jk + r * 8;
                float v0 = (k0 < 32)     ? WxG[ch * XX + k0]     : WhG[ch * HH + (k0 - 32)];
                float v1 = (k0 + 1 < 32) ? WxG[ch * XX + k0 + 1] : WhG[ch * HH + (k0 + 1 - 32)];
                __nv_bfloat16 h0, l0, h1, l1;
                bsplit(v0, h0, l0);
                bsplit(v1, h1, l1);
                Bh[kt][nt][r] = bfpack(h0, h1);
                Bl[kt][nt][r] = bfpack(l0, l1);
            }
        }
    }

    // ---- phase-B constants: my 4 channels = 8w + 2nt + (jk>>2), row jn+8pr ----
    const int chd = jk >> 2;   // 0 or 1
    float bI[4], bF[4], bN[4], bO[4], wic[4], wfc[4], woc[4];
    #pragma unroll
    for (int nt = 0; nt < 4; nt++) {
        const int ch = 8 * w + 2 * nt + chd;
        bI[nt] = ig_b[ch];  bF[nt] = fg_b[ch];
        bN[nt] = in_b[ch];  bO[nt] = og_b[ch];
        wic[nt] = ig_w_c[ch]; wfc[nt] = fg_w_c[ch]; woc[nt] = og_w_cn[ch];
    }
    float cm[4] = {0.0f, 0.0f, 0.0f, 0.0f};
    const int prow = jn + 8 * pr;   // my phase-B row

    // x loader: 2 values/thread (16 rows x 32 k = 512)
    const int xrow = tid >> 4;          // 0..15
    const int xc2  = (tid & 15) * 2;    // even 0..30
    const float* xptr = x + ((size_t)(b0 + xrow) * NN) * XX + xc2;

    // ---- prologue: zero Ah[0]; deposit x(0)->slot0, x(1)->slot1 ----
    for (int i = tid; i < TILE_B * AHP; i += THREADS) {
        (&Ahhi[0][0][0])[i] = __float2bfloat16_rn(0.0f);
        (&Ahlo[0][0][0])[i] = __float2bfloat16_rn(0.0f);
    }
    #pragma unroll
    for (int s = 0; s < 2; s++) {
        float2 xv = *reinterpret_cast<const float2*>(xptr + (size_t)s * XX);
        __nv_bfloat16 h0, l0, h1, l1;
        bsplit(xv.x, h0, l0);
        bsplit(xv.y, h1, l1);
        *reinterpret_cast<unsigned*>(&Axhi[s][xrow][xc2]) = bfpack(h0, h1);
        *reinterpret_cast<unsigned*>(&Axlo[s][xrow][xc2]) = bfpack(l0, l1);
    }
    __syncthreads();

    float acc[4][4];
    unsigned a[4];

    // x-contrib(0) from slot 0
    #pragma unroll
    for (int nt = 0; nt < 4; nt++)
        #pragma unroll
        for (int i = 0; i < 4; i++) acc[nt][i] = 0.0f;
    #pragma unroll
    for (int kt = 0; kt < 2; kt++) {
        const int kc = kt * 16 + jk;
        a[0] = *reinterpret_cast<const unsigned*>(&Axhi[0][jn][kc]);
        a[1] = *reinterpret_cast<const unsigned*>(&Axhi[0][jn + 8][kc]);
        a[2] = *reinterpret_cast<const unsigned*>(&Axhi[0][jn][kc + 8]);
        a[3] = *reinterpret_cast<const unsigned*>(&Axhi[0][jn + 8][kc + 8]);
        #pragma unroll
        for (int nt = 0; nt < 4; nt++) mma16816(acc[nt], a, Bh[kt][nt]);
        #pragma unroll
        for (int nt = 0; nt < 4; nt++) mma16816(acc[nt], a, Bl[kt][nt]);
        a[0] = *reinterpret_cast<const unsigned*>(&Axlo[0][jn][kc]);
        a[1] = *reinterpret_cast<const unsigned*>(&Axlo[0][jn + 8][kc]);
        a[2] = *reinterpret_cast<const unsigned*>(&Axlo[0][jn][kc + 8]);
        a[3] = *reinterpret_cast<const unsigned*>(&Axlo[0][jn + 8][kc + 8]);
        #pragma unroll
        for (int nt = 0; nt < 4; nt++) mma16816(acc[nt], a, Bh[kt][nt]);
    }

    int sl_r = 1;   // slot of x(t+1) at t=0
    int sl_w = 2;   // slot for x(t+2) at t=0

    for (int t = 0; t < NN; t++) {
        const int buf  = t & 1;
        const int nbuf = buf ^ 1;

        // prefetch x(t+2) for this iteration's deposit
        float2 xf = make_float2(0.0f, 0.0f);
        if (t + 2 < NN)
            xf = *reinterpret_cast<const float2*>(xptr + (size_t)(t + 2) * XX);

        // ---- h-MMA (kt 2..5): acc += h-projection; acc held x-contrib(t) ----
        #pragma unroll
        for (int kt = 2; kt < 6; kt++) {
            const int hc = (kt - 2) * 16 + jk;
            a[0] = *reinterpret_cast<const unsigned*>(&Ahhi[buf][jn][hc]);
            a[1] = *reinterpret_cast<const unsigned*>(&Ahhi[buf][jn + 8][hc]);
            a[2] = *reinterpret_cast<const unsigned*>(&Ahhi[buf][jn][hc + 8]);
            a[3] = *reinterpret_cast<const unsigned*>(&Ahhi[buf][jn + 8][hc + 8]);
            #pragma unroll
            for (int nt = 0; nt < 4; nt++) mma16816(acc[nt], a, Bh[kt][nt]);
            #pragma unroll
            for (int nt = 0; nt < 4; nt++) mma16816(acc[nt], a, Bl[kt][nt]);
        }
        #pragma unroll
        for (int kt = 2; kt < 6; kt++) {
            const int hc = (kt - 2) * 16 + jk;
            a[0] = *reinterpret_cast<const unsigned*>(&Ahlo[buf][jn][hc]);
            a[1] = *reinterpret_cast<const unsigned*>(&Ahlo[buf][jn + 8][hc]);
            a[2] = *reinterpret_cast<const unsigned*>(&Ahlo[buf][jn][hc + 8]);
            a[3] = *reinterpret_cast<const unsigned*>(&Ahlo[buf][jn + 8][hc + 8]);
            #pragma unroll
            for (int nt = 0; nt < 4; nt++) mma16816(acc[nt], a, Bh[kt][nt]);
        }

        // ---- gate exchange with lane^1: my row's missing gate pair ----
        // own pair for my row:   acc[nt][2*pr], acc[nt][2*pr+1]
        // send partner's row:    acc[nt][2*(1-pr)], acc[nt][2*(1-pr)+1]
        float gI[4], gF[4], gN[4], gO[4];
        #pragma unroll
        for (int nt = 0; nt < 4; nt++) {
            const int qo = 2 * pr;
            const int qs = 2 * (1 - pr);
            unsigned long long sv = packf2(acc[nt][qs], acc[nt][qs + 1]);
            unsigned long long rv = __shfl_xor_sync(0xffffffffu, sv, 1);
            float rx, ry;
            unpackf2(rv, rx, ry);
            const float ox = acc[nt][qo], oy = acc[nt][qo + 1];
            gI[nt] = sel01 ? ox : rx;
            gF[nt] = sel01 ? oy : ry;
            gN[nt] = sel01 ? rx : ox;
            gO[nt] = sel01 ? ry : oy;
        }

        // ---- deposit x(t+2) into slot sl_w ----
        if (t + 2 < NN) {
            __nv_bfloat16 h0, l0, h1, l1;
            bsplit(xf.x, h0, l0);
            bsplit(xf.y, h1, l1);
            *reinterpret_cast<unsigned*>(&Axhi[sl_w][xrow][xc2]) = bfpack(h0, h1);
            *reinterpret_cast<unsigned*>(&Axlo[sl_w][xrow][xc2]) = bfpack(l0, l1);
        }

        // ---- x-MMA(t+1) from slot sl_r (deposited last iteration) ----
        #pragma unroll
        for (int nt = 0; nt < 4; nt++)
            #pragma unroll
            for (int i = 0; i < 4; i++) acc[nt][i] = 0.0f;
        if (t + 1 < NN) {
            #pragma unroll
            for (int kt = 0; kt < 2; kt++) {
                const int kc = kt * 16 + jk;
                a[0] = *reinterpret_cast<const unsigned*>(&Axhi[sl_r][jn][kc]);
                a[1] = *reinterpret_cast<const unsigned*>(&Axhi[sl_r][jn + 8][kc]);
                a[2] = *reinterpret_cast<const unsigned*>(&Axhi[sl_r][jn][kc + 8]);
                a[3] = *reinterpret_cast<const unsigned*>(&Axhi[sl_r][jn + 8][kc + 8]);
                #pragma unroll
                for (int nt = 0; nt < 4; nt++) mma16816(acc[nt], a, Bh[kt][nt]);
                #pragma unroll
                for (int nt = 0; nt < 4; nt++) mma16816(acc[nt], a, Bl[kt][nt]);
                a[0] = *reinterpret_cast<const unsigned*>(&Axlo[sl_r][jn][kc]);
                a[1] = *reinterpret_cast<const unsigned*>(&Axlo[sl_r][jn + 8][kc]);
                a[2] = *reinterpret_cast<const unsigned*>(&Axlo[sl_r][jn][kc + 8]);
                a[3] = *reinterpret_cast<const unsigned*>(&Axlo[sl_r][jn + 8][kc + 8]);
                #pragma unroll
                for (int nt = 0; nt < 4; nt++) mma16816(acc[nt], a, Bh[kt][nt]);
            }
        }

        // ---- phase B: 4 (row=prow, ch) elements; cm in regs; write h ----
        #pragma unroll
        for (int nt = 0; nt < 4; nt++) {
            const int ch = 8 * w + 2 * nt + chd;
            const float cmv = cm[nt];
            const float ig  = sigmoidf_fast(wic[nt] * cmv + gI[nt] + bI[nt]);
            const float fg  = sigmoidf_fast(wfc[nt] * cmv + gF[nt] + bF[nt]);
            const float inn = tanhf_fast(gN[nt] + bN[nt]);
            const float cmn = fg * cmv + ig * inn;
            const float og  = sigmoidf_fast(woc[nt] * cmn + gO[nt] + bO[nt]);
            const float hv  = og * tanhf_fast(cmn);
            cm[nt] = cmn;
            __nv_bfloat16 h0, l0;
            bsplit(hv, h0, l0);
            Ahhi[nbuf][prow][ch] = h0;
            Ahlo[nbuf][prow][ch] = l0;
            if (t == NN - 1)
                out[(size_t)(b0 + prow) * HH + ch] = hv;
        }

        // rotate x slots
        sl_r = (sl_r == 2) ? 0 : sl_r + 1;
        sl_w = (sl_w == 2) ? 0 : sl_w + 1;

        __syncthreads();   // sole barrier: h(t+1), x deposits visible for t+1
    }
}

extern "C" void kernel_launch(void* const* d_in, const int* in_sizes, int n_in,
                              void* d_out, int out_size) {
    const float* x       = (const float*)d_in[0];
    const float* ig_w_c  = (const float*)d_in[1];
    const float* ig_w_h  = (const float*)d_in[2];
    const float* ig_w_x  = (const float*)d_in[3];
    const float* ig_b    = (const float*)d_in[4];
    const float* fg_w_c  = (const float*)d_in[5];
    const float* fg_w_h  = (const float*)d_in[6];
    const float* fg_w_x  = (const float*)d_in[7];
    const float* fg_b    = (const float*)d_in[8];
    const float* in_w_h  = (const float*)d_in[9];
    const float* in_w_x  = (const float*)d_in[10];
    const float* in_b    = (const float*)d_in[11];
    const float* og_w_cn = (const float*)d_in[12];
    const float* og_w_h  = (const float*)d_in[13];
    const float* og_w_x  = (const float*)d_in[14];
    const float* og_b    = (const float*)d_in[15];
    float* out = (float*)d_out;

    timelstm_tc_kernel<<<NBLK, THREADS>>>(
        x, ig_w_c, ig_w_h, ig_w_x, ig_b,
        fg_w_c, fg_w_h, fg_w_x, fg_b,
        in_w_h, in_w_x, in_b,
        og_w_cn, og_w_h, og_w_x, og_b, out);
}

// round 16
// speedup vs baseline: 1.2733x; 1.2733x over previous
#include <cuda_runtime.h>
#include <cuda_bf16.h>
#include <cstddef>

#define BB 2048
#define NN 512
#define XX 32
#define HH 64
#define TILE_B 16
#define THREADS 256
#define NBLK (BB / TILE_B)   /* 128 */
#define AXP 40               /* x operand pitch (bf16): 80B rows */
#define AHP 72               /* h operand pitch (bf16): 144B rows */
#define GPITCH 72            /* f32 per row in g_sh */

__device__ __forceinline__ float sigmoidf_fast(float x) {
    return __fdividef(1.0f, 1.0f + __expf(-x));
}
__device__ __forceinline__ float tanhf_fast(float x) {
    return __fdividef(2.0f, 1.0f + __expf(-2.0f * x)) - 1.0f;
}
__device__ __forceinline__ unsigned bfpack(__nv_bfloat16 a, __nv_bfloat16 b) {
    __nv_bfloat162 t;
    t.x = a; t.y = b;
    return *reinterpret_cast<unsigned*>(&t);
}
__device__ __forceinline__ void bsplit(float v, __nv_bfloat16& bh, __nv_bfloat16& bl) {
    bh = __float2bfloat16_rn(v);
    bl = __float2bfloat16_rn(v - __bfloat162float(bh));
}
__device__ __forceinline__ void mma16816(float* c, const unsigned* a, const unsigned* b) {
    asm volatile(
        "mma.sync.aligned.m16n8k16.row.col.f32.bf16.bf16.f32 "
        "{%0,%1,%2,%3}, {%4,%5,%6,%7}, {%8,%9}, {%0,%1,%2,%3};"
        : "+f"(c[0]), "+f"(c[1]), "+f"(c[2]), "+f"(c[3])
        : "r"(a[0]), "r"(a[1]), "r"(a[2]), "r"(a[3]), "r"(b[0]), "r"(b[1]));
}
// ldmatrix x4: loads the full m16k16 bf16 A fragment (4 regs) in one op
__device__ __forceinline__ void ldsm4(unsigned* a, unsigned saddr) {
    asm volatile(
        "ldmatrix.sync.aligned.m8n8.x4.shared.b16 {%0,%1,%2,%3}, [%4];"
        : "=r"(a[0]), "=r"(a[1]), "=r"(a[2]), "=r"(a[3]) : "r"(saddr));
}

__global__ void __launch_bounds__(THREADS, 1)
timelstm_tc_kernel(const float* __restrict__ x,
                   const float* __restrict__ ig_w_c, const float* __restrict__ ig_w_h,
                   const float* __restrict__ ig_w_x, const float* __restrict__ ig_b,
                   const float* __restrict__ fg_w_c, const float* __restrict__ fg_w_h,
                   const float* __restrict__ fg_w_x, const float* __restrict__ fg_b,
                   const float* __restrict__ in_w_h, const float* __restrict__ in_w_x,
                   const float* __restrict__ in_b,
                   const float* __restrict__ og_w_cn, const float* __restrict__ og_w_h,
                   const float* __restrict__ og_w_x, const float* __restrict__ og_b,
                   float* __restrict__ out)
{
    __shared__ __align__(16) __nv_bfloat16 Axhi[2][TILE_B][AXP];
    __shared__ __align__(16) __nv_bfloat16 Axlo[2][TILE_B][AXP];
    __shared__ __align__(16) __nv_bfloat16 Ahhi[2][TILE_B][AHP];
    __shared__ __align__(16) __nv_bfloat16 Ahlo[2][TILE_B][AHP];
    __shared__ float g_sh[4][TILE_B][GPITCH];

    const int tid  = threadIdx.x;
    const int b0   = blockIdx.x * TILE_B;
    const int warp = tid >> 5;
    const int lane = tid & 31;
    const int gate  = warp >> 1;     // 0 ig, 1 fg, 2 in, 3 og
    const int nhalf = warp & 1;
    const int jn = lane >> 2;
    const int jk = (lane & 3) * 2;

    const float *Wh, *Wx;
    if (gate == 0)      { Wh = ig_w_h; Wx = ig_w_x; }
    else if (gate == 1) { Wh = fg_w_h; Wx = fg_w_x; }
    else if (gate == 2) { Wh = in_w_h; Wx = in_w_x; }
    else                { Wh = og_w_h; Wx = og_w_x; }

    // ---- B fragments: kt 0..1 = x-part, kt 2..5 = h-part ----
    unsigned Bh[6][4][2], Bl[6][4][2];
    #pragma unroll
    for (int kt = 0; kt < 6; kt++) {
        #pragma unroll
        for (int nt = 0; nt < 4; nt++) {
            const int ch = nhalf * 32 + nt * 8 + jn;
            #pragma unroll
            for (int r = 0; r < 2; r++) {
                const int k0 = kt * 16 + jk + r * 8;
                float v0 = (k0 < 32)     ? Wx[ch * XX + k0]     : Wh[ch * HH + (k0 - 32)];
                float v1 = (k0 + 1 < 32) ? Wx[ch * XX + k0 + 1] : Wh[ch * HH + (k0 + 1 - 32)];
                __nv_bfloat16 h0, l0, h1, l1;
                bsplit(v0, h0, l0);
                bsplit(v1, h1, l1);
                Bh[kt][nt][r] = bfpack(h0, h1);
                Bl[kt][nt][r] = bfpack(l0, l1);
            }
        }
    }

    // ---- phase-B constants ----
    const int rg = tid >> 5;
    const int pc = (tid & 31) * 2;
    float bI[2], bF[2], bN[2], bO[2], wic[2], wfc[2], woc[2];
    #pragma unroll
    for (int c = 0; c < 2; c++) {
        bI[c] = ig_b[pc + c];  bF[c] = fg_b[pc + c];
        bN[c] = in_b[pc + c];  bO[c] = og_b[pc + c];
        wic[c] = ig_w_c[pc + c]; wfc[c] = fg_w_c[pc + c]; woc[c] = og_w_cn[pc + c];
    }
    float cm[2][2] = {{0.0f, 0.0f}, {0.0f, 0.0f}};

    // x loader mapping
    const int xrow = tid >> 4;
    const int xc2  = (tid & 15) * 2;
    const float* xptr = x + ((size_t)(b0 + xrow) * NN) * XX + xc2;

    // ---- ldmatrix per-thread row/half offsets ----
    const int lrow = (lane & 7) + 8 * ((lane >> 3) & 1);   // matrix row
    const int lhalf = lane >> 4;                           // k-half (0/1)
    const unsigned sAxhi = (unsigned)__cvta_generic_to_shared(&Axhi[0][0][0]);
    const unsigned sAxlo = (unsigned)__cvta_generic_to_shared(&Axlo[0][0][0]);
    const unsigned sAhhi = (unsigned)__cvta_generic_to_shared(&Ahhi[0][0][0]);
    const unsigned sAhlo = (unsigned)__cvta_generic_to_shared(&Ahlo[0][0][0]);
    const unsigned xoff = (unsigned)(lrow * (AXP * 2) + lhalf * 16);
    const unsigned hoff = (unsigned)(lrow * (AHP * 2) + lhalf * 16);
    const unsigned xbufsz = TILE_B * AXP * 2;   // bytes per Ax buffer
    const unsigned hbufsz = TILE_B * AHP * 2;   // bytes per Ah buffer

    // ---- prologue: zero Ah[0]; deposit x(0) into Ax[0] ----
    for (int i = tid; i < TILE_B * AHP; i += THREADS) {
        (&Ahhi[0][0][0])[i] = __float2bfloat16_rn(0.0f);
        (&Ahlo[0][0][0])[i] = __float2bfloat16_rn(0.0f);
    }
    {
        float2 xv = *reinterpret_cast<const float2*>(xptr);
        __nv_bfloat16 h0, l0, h1, l1;
        bsplit(xv.x, h0, l0);
        bsplit(xv.y, h1, l1);
        *reinterpret_cast<unsigned*>(&Axhi[0][xrow][xc2]) = bfpack(h0, h1);
        *reinterpret_cast<unsigned*>(&Axlo[0][xrow][xc2]) = bfpack(l0, l1);
    }
    __syncthreads();

    // dual accumulators: accA = hi*hi + lo*hi terms, accB = hi*lo terms
    float accA[4][4], accB[4][4];
    unsigned a[4];

    // x-contrib(0) from Ax[0]
    #pragma unroll
    for (int nt = 0; nt < 4; nt++)
        #pragma unroll
        for (int i = 0; i < 4; i++) { accA[nt][i] = 0.0f; accB[nt][i] = 0.0f; }
    #pragma unroll
    for (int kt = 0; kt < 2; kt++) {
        ldsm4(a, sAxhi + xoff + kt * 32);
        #pragma unroll
        for (int nt = 0; nt < 4; nt++) mma16816(accA[nt], a, Bh[kt][nt]);
        #pragma unroll
        for (int nt = 0; nt < 4; nt++) mma16816(accB[nt], a, Bl[kt][nt]);
        ldsm4(a, sAxlo + xoff + kt * 32);
        #pragma unroll
        for (int nt = 0; nt < 4; nt++) mma16816(accA[nt], a, Bh[kt][nt]);
    }
    // prefetch x(1)
    float2 xn = *reinterpret_cast<const float2*>(xptr + (size_t)1 * XX);

    for (int t = 0; t < NN; t++) {
        const int buf  = t & 1;
        const int nbuf = buf ^ 1;

        // ---- W1: deposit x(t+1); h-MMA (kt 2..5) ----
        {
            __nv_bfloat16 h0, l0, h1, l1;
            bsplit(xn.x, h0, l0);
            bsplit(xn.y, h1, l1);
            *reinterpret_cast<unsigned*>(&Axhi[nbuf][xrow][xc2]) = bfpack(h0, h1);
            *reinterpret_cast<unsigned*>(&Axlo[nbuf][xrow][xc2]) = bfpack(l0, l1);
        }

        const unsigned hbase = buf * hbufsz;
        #pragma unroll
        for (int kt = 2; kt < 6; kt++) {
            ldsm4(a, sAhhi + hbase + hoff + (kt - 2) * 32);
            #pragma unroll
            for (int nt = 0; nt < 4; nt++) mma16816(accA[nt], a, Bh[kt][nt]);
            #pragma unroll
            for (int nt = 0; nt < 4; nt++) mma16816(accB[nt], a, Bl[kt][nt]);
        }
        #pragma unroll
        for (int kt = 2; kt < 6; kt++) {
            ldsm4(a, sAhlo + hbase + hoff + (kt - 2) * 32);
            #pragma unroll
            for (int nt = 0; nt < 4; nt++) mma16816(accA[nt], a, Bh[kt][nt]);
        }

        // scatter D frags (sum dual accs) to g_sh
        #pragma unroll
        for (int nt = 0; nt < 4; nt++) {
            const int ch = nhalf * 32 + nt * 8 + jk;
            *reinterpret_cast<float2*>(&g_sh[gate][jn][ch]) =
                make_float2(accA[nt][0] + accB[nt][0], accA[nt][1] + accB[nt][1]);
            *reinterpret_cast<float2*>(&g_sh[gate][jn + 8][ch]) =
                make_float2(accA[nt][2] + accB[nt][2], accA[nt][3] + accB[nt][3]);
        }
        __syncthreads();   // B1: g_sh + x(t+1) deposits visible

        // ---- W2: phase B (MUFU) overlapped with x-MMA(t+1) (tensor) ----
        if (t + 2 < NN)
            xn = *reinterpret_cast<const float2*>(xptr + (size_t)(t + 2) * XX);

        #pragma unroll
        for (int nt = 0; nt < 4; nt++)
            #pragma unroll
            for (int i = 0; i < 4; i++) { accA[nt][i] = 0.0f; accB[nt][i] = 0.0f; }
        if (t + 1 < NN) {
            const unsigned xbase = nbuf * xbufsz;
            #pragma unroll
            for (int kt = 0; kt < 2; kt++) {
                ldsm4(a, sAxhi + xbase + xoff + kt * 32);
                #pragma unroll
                for (int nt = 0; nt < 4; nt++) mma16816(accA[nt], a, Bh[kt][nt]);
                #pragma unroll
                for (int nt = 0; nt < 4; nt++) mma16816(accB[nt], a, Bl[kt][nt]);
                ldsm4(a, sAxlo + xbase + xoff + kt * 32);
                #pragma unroll
                for (int nt = 0; nt < 4; nt++) mma16816(accA[nt], a, Bh[kt][nt]);
            }
        }

        // phase B: activations + state update
        float hnew[2][2];
        #pragma unroll
        for (int e = 0; e < 2; e++) {
            const int r = rg + 8 * e;
            #pragma unroll
            for (int c = 0; c < 2; c++) {
                const int ch = pc + c;
                const float cmv = cm[e][c];
                const float ig  = sigmoidf_fast(wic[c] * cmv + g_sh[0][r][ch] + bI[c]);
                const float fg  = sigmoidf_fast(wfc[c] * cmv + g_sh[1][r][ch] + bF[c]);
                const float inn = tanhf_fast(g_sh[2][r][ch] + bN[c]);
                const float cmn = fg * cmv + ig * inn;
                const float og  = sigmoidf_fast(woc[c] * cmn + g_sh[3][r][ch] + bO[c]);
                hnew[e][c] = og * tanhf_fast(cmn);
                cm[e][c] = cmn;
            }
            __nv_bfloat16 h0, l0, h1, l1;
            bsplit(hnew[e][0], h0, l0);
            bsplit(hnew[e][1], h1, l1);
            *reinterpret_cast<unsigned*>(&Ahhi[nbuf][r][pc]) = bfpack(h0, h1);
            *reinterpret_cast<unsigned*>(&Ahlo[nbuf][r][pc]) = bfpack(l0, l1);
        }
        if (t == NN - 1) {
            *reinterpret_cast<float2*>(&out[(size_t)(b0 + rg) * HH + pc]) =
                make_float2(hnew[0][0], hnew[0][1]);
            *reinterpret_cast<float2*>(&out[(size_t)(b0 + rg + 8) * HH + pc]) =
                make_float2(hnew[1][0], hnew[1][1]);
        }
        __syncthreads();   // B2: h(t+1) ready; x-MMA reads of Ax[nbuf] complete
    }
}

extern "C" void kernel_launch(void* const* d_in, const int* in_sizes, int n_in,
                              void* d_out, int out_size) {
    const float* x       = (const float*)d_in[0];
    const float* ig_w_c  = (const float*)d_in[1];
    const float* ig_w_h  = (const float*)d_in[2];
    const float* ig_w_x  = (const float*)d_in[3];
    const float* ig_b    = (const float*)d_in[4];
    const float* fg_w_c  = (const float*)d_in[5];
    const float* fg_w_h  = (const float*)d_in[6];
    const float* fg_w_x  = (const float*)d_in[7];
    const float* fg_b    = (const float*)d_in[8];
    const float* in_w_h  = (const float*)d_in[9];
    const float* in_w_x  = (const float*)d_in[10];
    const float* in_b    = (const float*)d_in[11];
    const float* og_w_cn = (const float*)d_in[12];
    const float* og_w_h  = (const float*)d_in[13];
    const float* og_w_x  = (const float*)d_in[14];
    const float* og_b    = (const float*)d_in[15];
    float* out = (float*)d_out;

    timelstm_tc_kernel<<<NBLK, THREADS>>>(
        x, ig_w_c, ig_w_h, ig_w_x, ig_b,
        fg_w_c, fg_w_h, fg_w_x, fg_b,
        in_w_h, in_w_x, in_b,
        og_w_cn, og_w_h, og_w_x, og_b, out);
}

// round 17
// speedup vs baseline: 1.7565x; 1.3795x over previous
#include <cuda_runtime.h>
#include <cuda_fp16.h>
#include <cstddef>

#define BB 2048
#define NN 512
#define XX 32
#define HH 64
#define TILE_B 16
#define THREADS 256
#define NBLK (BB / TILE_B)   /* 128 */
#define AXP 40               /* x operand pitch (fp16): 80B rows */
#define AHP 72               /* h operand pitch (fp16): 144B rows */
#define GPITCH 72            /* f32 per row in g_sh */
#define WLSCALE 2048.0f      /* Wl pre-scale (2^11), recombined as /2048 */

__device__ __forceinline__ float sigmoidf_fast(float x) {
    return __fdividef(1.0f, 1.0f + __expf(-x));
}
__device__ __forceinline__ float tanhf_fast(float x) {
    return __fdividef(2.0f, 1.0f + __expf(-2.0f * x)) - 1.0f;
}
__device__ __forceinline__ unsigned h2pack(__half a, __half b) {
    __half2 t;
    t.x = a; t.y = b;
    return *reinterpret_cast<unsigned*>(&t);
}
__device__ __forceinline__ void mma16816(float* c, const unsigned* a, const unsigned* b) {
    asm volatile(
        "mma.sync.aligned.m16n8k16.row.col.f32.f16.f16.f32 "
        "{%0,%1,%2,%3}, {%4,%5,%6,%7}, {%8,%9}, {%0,%1,%2,%3};"
        : "+f"(c[0]), "+f"(c[1]), "+f"(c[2]), "+f"(c[3])
        : "r"(a[0]), "r"(a[1]), "r"(a[2]), "r"(a[3]), "r"(b[0]), "r"(b[1]));
}
__device__ __forceinline__ void ldsm4(unsigned* a, unsigned saddr) {
    asm volatile(
        "ldmatrix.sync.aligned.m8n8.x4.shared.b16 {%0,%1,%2,%3}, [%4];"
        : "=r"(a[0]), "=r"(a[1]), "=r"(a[2]), "=r"(a[3]) : "r"(saddr));
}

__global__ void __launch_bounds__(THREADS, 1)
timelstm_tc_kernel(const float* __restrict__ x,
                   const float* __restrict__ ig_w_c, const float* __restrict__ ig_w_h,
                   const float* __restrict__ ig_w_x, const float* __restrict__ ig_b,
                   const float* __restrict__ fg_w_c, const float* __restrict__ fg_w_h,
                   const float* __restrict__ fg_w_x, const float* __restrict__ fg_b,
                   const float* __restrict__ in_w_h, const float* __restrict__ in_w_x,
                   const float* __restrict__ in_b,
                   const float* __restrict__ og_w_cn, const float* __restrict__ og_w_h,
                   const float* __restrict__ og_w_x, const float* __restrict__ og_b,
                   float* __restrict__ out)
{
    // fp16 operands: x ping-pong, h ping-pong (single precision level, no lo arrays)
    __shared__ __align__(16) __half Axh[2][TILE_B][AXP];
    __shared__ __align__(16) __half Ahh[2][TILE_B][AHP];
    __shared__ float g_sh[4][TILE_B][GPITCH];

    const int tid  = threadIdx.x;
    const int b0   = blockIdx.x * TILE_B;
    const int warp = tid >> 5;
    const int lane = tid & 31;
    const int gate  = warp >> 1;     // 0 ig, 1 fg, 2 in, 3 og
    const int nhalf = warp & 1;
    const int jn = lane >> 2;
    const int jk = (lane & 3) * 2;

    const float *Wh, *Wx;
    if (gate == 0)      { Wh = ig_w_h; Wx = ig_w_x; }
    else if (gate == 1) { Wh = fg_w_h; Wx = fg_w_x; }
    else if (gate == 2) { Wh = in_w_h; Wx = in_w_x; }
    else                { Wh = og_w_h; Wx = og_w_x; }

    // ---- B fragments: W = Bh + Bl/2048 (Bl pre-scaled into fp16 normal range) ----
    unsigned Bhf[6][4][2], Blf[6][4][2];
    #pragma unroll
    for (int kt = 0; kt < 6; kt++) {
        #pragma unroll
        for (int nt = 0; nt < 4; nt++) {
            const int ch = nhalf * 32 + nt * 8 + jn;
            #pragma unroll
            for (int r = 0; r < 2; r++) {
                const int k0 = kt * 16 + jk + r * 8;
                float v0 = (k0 < 32)     ? Wx[ch * XX + k0]     : Wh[ch * HH + (k0 - 32)];
                float v1 = (k0 + 1 < 32) ? Wx[ch * XX + k0 + 1] : Wh[ch * HH + (k0 + 1 - 32)];
                __half h0 = __float2half_rn(v0);
                __half h1 = __float2half_rn(v1);
                __half l0 = __float2half_rn((v0 - __half2float(h0)) * WLSCALE);
                __half l1 = __float2half_rn((v1 - __half2float(h1)) * WLSCALE);
                Bhf[kt][nt][r] = h2pack(h0, h1);
                Blf[kt][nt][r] = h2pack(l0, l1);
            }
        }
    }

    // ---- phase-B constants ----
    const int rg = tid >> 5;
    const int pc = (tid & 31) * 2;
    float bI[2], bF[2], bN[2], bO[2], wic[2], wfc[2], woc[2];
    #pragma unroll
    for (int c = 0; c < 2; c++) {
        bI[c] = ig_b[pc + c];  bF[c] = fg_b[pc + c];
        bN[c] = in_b[pc + c];  bO[c] = og_b[pc + c];
        wic[c] = ig_w_c[pc + c]; wfc[c] = fg_w_c[pc + c]; woc[c] = og_w_cn[pc + c];
    }
    float cm[2][2] = {{0.0f, 0.0f}, {0.0f, 0.0f}};

    // x loader mapping
    const int xrow = tid >> 4;
    const int xc2  = (tid & 15) * 2;
    const float* xptr = x + ((size_t)(b0 + xrow) * NN) * XX + xc2;

    // ---- ldmatrix per-thread offsets (byte pitches: x 80B, h 144B) ----
    const int lrow = (lane & 7) + 8 * ((lane >> 3) & 1);
    const int lhalf = lane >> 4;
    const unsigned sAxh = (unsigned)__cvta_generic_to_shared(&Axh[0][0][0]);
    const unsigned sAhh = (unsigned)__cvta_generic_to_shared(&Ahh[0][0][0]);
    const unsigned xoff = (unsigned)(lrow * (AXP * 2) + lhalf * 16);
    const unsigned hoff = (unsigned)(lrow * (AHP * 2) + lhalf * 16);
    const unsigned xbufsz = TILE_B * AXP * 2;
    const unsigned hbufsz = TILE_B * AHP * 2;

    // ---- prologue: zero Ah[0]; deposit x(0) into Ax[0] ----
    for (int i = tid; i < TILE_B * AHP; i += THREADS)
        (&Ahh[0][0][0])[i] = __float2half_rn(0.0f);
    {
        float2 xv = *reinterpret_cast<const float2*>(xptr);
        *reinterpret_cast<unsigned*>(&Axh[0][xrow][xc2]) =
            h2pack(__float2half_rn(xv.x), __float2half_rn(xv.y));
    }
    __syncthreads();

    float accA[4][4], accB[4][4];
    unsigned a[4];

    // x-contrib(0) from Ax[0]
    #pragma unroll
    for (int nt = 0; nt < 4; nt++)
        #pragma unroll
        for (int i = 0; i < 4; i++) { accA[nt][i] = 0.0f; accB[nt][i] = 0.0f; }
    #pragma unroll
    for (int kt = 0; kt < 2; kt++) {
        ldsm4(a, sAxh + xoff + kt * 32);
        #pragma unroll
        for (int nt = 0; nt < 4; nt++) mma16816(accA[nt], a, Bhf[kt][nt]);
        #pragma unroll
        for (int nt = 0; nt < 4; nt++) mma16816(accB[nt], a, Blf[kt][nt]);
    }
    // prefetch x(1)
    float2 xn = *reinterpret_cast<const float2*>(xptr + (size_t)1 * XX);

    const float wls = 1.0f / WLSCALE;

    for (int t = 0; t < NN; t++) {
        const int buf  = t & 1;
        const int nbuf = buf ^ 1;

        // ---- W1: deposit x(t+1); h-MMA (kt 2..5), 2 terms ----
        *reinterpret_cast<unsigned*>(&Axh[nbuf][xrow][xc2]) =
            h2pack(__float2half_rn(xn.x), __float2half_rn(xn.y));

        const unsigned hbase = buf * hbufsz;
        #pragma unroll
        for (int kt = 2; kt < 6; kt++) {
            ldsm4(a, sAhh + hbase + hoff + (kt - 2) * 32);
            #pragma unroll
            for (int nt = 0; nt < 4; nt++) mma16816(accA[nt], a, Bhf[kt][nt]);
            #pragma unroll
            for (int nt = 0; nt < 4; nt++) mma16816(accB[nt], a, Blf[kt][nt]);
        }

        // scatter D frags (accA + accB/2048) to g_sh
        #pragma unroll
        for (int nt = 0; nt < 4; nt++) {
            const int ch = nhalf * 32 + nt * 8 + jk;
            *reinterpret_cast<float2*>(&g_sh[gate][jn][ch]) =
                make_float2(fmaf(accB[nt][0], wls, accA[nt][0]),
                            fmaf(accB[nt][1], wls, accA[nt][1]));
            *reinterpret_cast<float2*>(&g_sh[gate][jn + 8][ch]) =
                make_float2(fmaf(accB[nt][2], wls, accA[nt][2]),
                            fmaf(accB[nt][3], wls, accA[nt][3]));
        }
        __syncthreads();   // B1: g_sh + x(t+1) deposits visible

        // ---- W2: phase B (MUFU) overlapped with x-MMA(t+1) (tensor) ----
        if (t + 2 < NN)
            xn = *reinterpret_cast<const float2*>(xptr + (size_t)(t + 2) * XX);

        #pragma unroll
        for (int nt = 0; nt < 4; nt++)
            #pragma unroll
            for (int i = 0; i < 4; i++) { accA[nt][i] = 0.0f; accB[nt][i] = 0.0f; }
        if (t + 1 < NN) {
            const unsigned xbase = nbuf * xbufsz;
            #pragma unroll
            for (int kt = 0; kt < 2; kt++) {
                ldsm4(a, sAxh + xbase + xoff + kt * 32);
                #pragma unroll
                for (int nt = 0; nt < 4; nt++) mma16816(accA[nt], a, Bhf[kt][nt]);
                #pragma unroll
                for (int nt = 0; nt < 4; nt++) mma16816(accB[nt], a, Blf[kt][nt]);
            }
        }

        // phase B: activations + state update
        float hnew[2][2];
        #pragma unroll
        for (int e = 0; e < 2; e++) {
            const int r = rg + 8 * e;
            #pragma unroll
            for (int c = 0; c < 2; c++) {
                const int ch = pc + c;
                const float cmv = cm[e][c];
                const float ig  = sigmoidf_fast(wic[c] * cmv + g_sh[0][r][ch] + bI[c]);
                const float fg  = sigmoidf_fast(wfc[c] * cmv + g_sh[1][r][ch] + bF[c]);
                const float inn = tanhf_fast(g_sh[2][r][ch] + bN[c]);
                const float cmn = fg * cmv + ig * inn;
                const float og  = sigmoidf_fast(woc[c] * cmn + g_sh[3][r][ch] + bO[c]);
                hnew[e][c] = og * tanhf_fast(cmn);
                cm[e][c] = cmn;
            }
            *reinterpret_cast<unsigned*>(&Ahh[nbuf][r][pc]) =
                h2pack(__float2half_rn(hnew[e][0]), __float2half_rn(hnew[e][1]));
        }
        if (t == NN - 1) {
            *reinterpret_cast<float2*>(&out[(size_t)(b0 + rg) * HH + pc]) =
                make_float2(hnew[0][0], hnew[0][1]);
            *reinterpret_cast<float2*>(&out[(size_t)(b0 + rg + 8) * HH + pc]) =
                make_float2(hnew[1][0], hnew[1][1]);
        }
        __syncthreads();   // B2: h(t+1) ready; x-MMA reads of Ax[nbuf] complete
    }
}

extern "C" void kernel_launch(void* const* d_in, const int* in_sizes, int n_in,
                              void* d_out, int out_size) {
    const float* x       = (const float*)d_in[0];
    const float* ig_w_c  = (const float*)d_in[1];
    const float* ig_w_h  = (const float*)d_in[2];
    const float* ig_w_x  = (const float*)d_in[3];
    const float* ig_b    = (const float*)d_in[4];
    const float* fg_w_c  = (const float*)d_in[5];
    const float* fg_w_h  = (const float*)d_in[6];
    const float* fg_w_x  = (const float*)d_in[7];
    const float* fg_b    = (const float*)d_in[8];
    const float* in_w_h  = (const float*)d_in[9];
    const float* in_w_x  = (const float*)d_in[10];
    const float* in_b    = (const float*)d_in[11];
    const float* og_w_cn = (const float*)d_in[12];
    const float* og_w_h  = (const float*)d_in[13];
    const float* og_w_x  = (const float*)d_in[14];
    const float* og_b    = (const float*)d_in[15];
    float* out = (float*)d_out;

    timelstm_tc_kernel<<<NBLK, THREADS>>>(
        x, ig_w_c, ig_w_h, ig_w_x, ig_b,
        fg_w_c, fg_w_h, fg_w_x, fg_b,
        in_w_h, in_w_x, in_b,
        og_w_cn, og_w_h, og_w_x, og_b, out);
}